// round 1
// baseline (speedup 1.0000x reference)
#include <cuda_runtime.h>
#include <math.h>

#define NH 6
#define NB 512
#define ND 2048
#define NC 1000
#define TAU 0.5f

// Scratch (no allocations allowed -> __device__ globals)
__device__ float g_logits[NH * NB * NC];   // [h][b][c]
__device__ float g_conf[NH * NB];          // max softmax prob per (h,b)
__device__ float g_logZ[NH * NB];          // logsumexp per (h,b)
__device__ int   g_amax[NH * NB];          // argmax class per (h,b)
__device__ float g_loss[NB];
__device__ float g_corr[NB];

// ---------------------------------------------------------------------------
// GEMM: logits[h,b,c] = feats[h,b,:] . W[h,:,c] + bias[h,c]
// 64x64 tile, BK=16, 256 threads, 4x4 per-thread micro-tile, fp32 FFMA.
// ---------------------------------------------------------------------------
#define BM 64
#define BN 64
#define BK 16

__global__ __launch_bounds__(256) void gemm_k(const float* __restrict__ feats,
                                              const float* __restrict__ Wt,
                                              const float* __restrict__ bias) {
    __shared__ float As[BK][BM + 4];
    __shared__ float Bs[BK][BN + 4];

    const int h  = blockIdx.z;
    const int m0 = blockIdx.y * BM;
    const int n0 = blockIdx.x * BN;
    const float* A  = feats + (size_t)h * NB * ND;
    const float* Bp = Wt    + (size_t)h * ND * NC;

    const int tid = threadIdx.x;
    const int tx  = tid & 15;        // 0..15  (N direction)
    const int ty  = tid >> 4;        // 0..15  (M direction)

    // A-tile load mapping: thread -> (row 0..63, kcol group 0..3)
    const int ar = tid >> 2;
    const int ak = (tid & 3) << 2;
    // B-tile load mapping: thread -> (krow 0..15, col group of 4)
    const int bkr = tid >> 4;
    const int bc  = (tid & 15) << 2;
    const int gc  = n0 + bc;

    float acc[4][4];
    #pragma unroll
    for (int i = 0; i < 4; i++)
        #pragma unroll
        for (int j = 0; j < 4; j++) acc[i][j] = 0.f;

    for (int kt = 0; kt < ND; kt += BK) {
        float4 av = *(const float4*)(A + (size_t)(m0 + ar) * ND + kt + ak);
        float4 bv = make_float4(0.f, 0.f, 0.f, 0.f);
        if (gc < NC)   // gc multiple of 4, NC multiple of 4 -> full vector in-bounds
            bv = *(const float4*)(Bp + (size_t)(kt + bkr) * NC + gc);

        __syncthreads();   // protect previous iteration's smem reads
        As[ak + 0][ar] = av.x;
        As[ak + 1][ar] = av.y;
        As[ak + 2][ar] = av.z;
        As[ak + 3][ar] = av.w;
        *(float4*)&Bs[bkr][bc] = bv;
        __syncthreads();

        #pragma unroll
        for (int k = 0; k < BK; k++) {
            float4 a = *(const float4*)&As[k][ty << 2];
            float4 b = *(const float4*)&Bs[k][tx << 2];
            float aa[4] = {a.x, a.y, a.z, a.w};
            float bb[4] = {b.x, b.y, b.z, b.w};
            #pragma unroll
            for (int i = 0; i < 4; i++)
                #pragma unroll
                for (int j = 0; j < 4; j++)
                    acc[i][j] += aa[i] * bb[j];
        }
    }

    #pragma unroll
    for (int i = 0; i < 4; i++) {
        const int m = m0 + (ty << 2) + i;
        #pragma unroll
        for (int j = 0; j < 4; j++) {
            const int c = n0 + (tx << 2) + j;
            if (c < NC)
                g_logits[((size_t)h * NB + m) * NC + c] = acc[i][j] + bias[h * NC + c];
        }
    }
}

// ---------------------------------------------------------------------------
// Per-row stats: max, argmax, logsumexp, confidence (= 1/sum exp(l-max))
// One block per (h,b) row.
// ---------------------------------------------------------------------------
__global__ __launch_bounds__(128) void rowstats_k() {
    const int row = blockIdx.x;                 // h*NB + b
    const float* lr = g_logits + (size_t)row * NC;
    const int tid = threadIdx.x;

    float vmax = -1e30f; int imax = 0;
    for (int c = tid; c < NC; c += 128) {
        float v = lr[c];
        if (v > vmax) { vmax = v; imax = c; }
    }
    __shared__ float sv[128];
    __shared__ int   si[128];
    sv[tid] = vmax; si[tid] = imax;
    __syncthreads();
    for (int s = 64; s > 0; s >>= 1) {
        if (tid < s) {
            float v2 = sv[tid + s]; int i2 = si[tid + s];
            if (v2 > sv[tid] || (v2 == sv[tid] && i2 < si[tid])) { sv[tid] = v2; si[tid] = i2; }
        }
        __syncthreads();
    }
    const float m = sv[0];
    const int  am = si[0];

    float sum = 0.f;
    for (int c = tid; c < NC; c += 128) sum += expf(lr[c] - m);
    __shared__ float ss[128];
    ss[tid] = sum;
    __syncthreads();
    for (int s = 64; s > 0; s >>= 1) {
        if (tid < s) ss[tid] += ss[tid + s];
        __syncthreads();
    }
    if (tid == 0) {
        const float s = ss[0];
        g_conf[row] = 1.f / s;          // exp(max-max)/sum = max softmax prob
        g_logZ[row] = m + logf(s);
        g_amax[row] = am;
    }
}

// ---------------------------------------------------------------------------
// Routing + gather + per-sample loss/acc. One block per sample b.
// Early exit: first head with conf >= TAU, else argmax-conf head (first tie).
// ---------------------------------------------------------------------------
__global__ __launch_bounds__(256) void route_k(const int* __restrict__ y_true,
                                               float* __restrict__ out) {
    const int b = blockIdx.x;

    int fh = -1, bh = 0;
    float bc = -1.f;
    #pragma unroll
    for (int hh = 0; hh < NH; hh++) {
        float cv = g_conf[hh * NB + b];
        if (fh < 0 && cv >= TAU) fh = hh;
        if (cv > bc) { bc = cv; bh = hh; }
    }
    const int e = (fh >= 0) ? fh : bh;

    const float* lr = g_logits + ((size_t)e * NB + b) * NC;
    const float4* src = (const float4*)lr;
    float4* dst = (float4*)(out + (size_t)b * NC);
    for (int i = threadIdx.x; i < NC / 4; i += 256) dst[i] = src[i];

    if (threadIdx.x == 0) {
        out[(size_t)NB * NC + b] = (float)e;          // exit_idx as float
        const int y = y_true[b];
        g_loss[b] = -(lr[y] - g_logZ[e * NB + b]);
        g_corr[b] = (g_amax[e * NB + b] == y) ? 1.f : 0.f;
    }
}

// ---------------------------------------------------------------------------
// Final reduction: mean loss, mean accuracy.
// ---------------------------------------------------------------------------
__global__ __launch_bounds__(512) void final_k(float* __restrict__ out) {
    __shared__ float sl[512];
    __shared__ float sc[512];
    const int t = threadIdx.x;
    sl[t] = g_loss[t];
    sc[t] = g_corr[t];
    __syncthreads();
    for (int s = 256; s > 0; s >>= 1) {
        if (t < s) { sl[t] += sl[t + s]; sc[t] += sc[t + s]; }
        __syncthreads();
    }
    if (t == 0) {
        out[(size_t)NB * NC + NB + 0] = sl[0] / (float)NB;   // loss
        out[(size_t)NB * NC + NB + 1] = sc[0] / (float)NB;   // acc
    }
}

extern "C" void kernel_launch(void* const* d_in, const int* in_sizes, int n_in,
                              void* d_out, int out_size) {
    const float* feats = (const float*)d_in[0];   // [6,512,2048]
    const float* Wt    = (const float*)d_in[1];   // [6,2048,1000]
    const float* bias  = (const float*)d_in[2];   // [6,1000]
    const int*   y     = (const int*)d_in[3];     // [512]
    float* out = (float*)d_out;

    dim3 g((NC + BN - 1) / BN, NB / BM, NH);      // 16 x 8 x 6 = 768 CTAs
    gemm_k<<<g, 256>>>(feats, Wt, bias);
    rowstats_k<<<NH * NB, 128>>>();
    route_k<<<NB, 256>>>(y, out);
    final_k<<<1, 512>>>(out);
}

// round 4
// speedup vs baseline: 2.0857x; 2.0857x over previous
#include <cuda_runtime.h>
#include <cuda_bf16.h>
#include <math.h>
#include <stdint.h>

#define NH 6
#define NB 512
#define ND 2048
#define NC 1000
#define NP 1024
#define TAU 0.5f

#define BK 32
#define NITER (ND / BK)          // 64
#define STAGES 3
#define STG_BYTES (32 * 1024)    // Ahi 8K | Alo 8K | Bhi 8K | Blo 8K
#define GSMEM (STAGES * STG_BYTES)

// ------------------------- scratch ------------------------------------------
__device__ __nv_bfloat16 g_Ahi[NH * NB * ND];
__device__ __nv_bfloat16 g_Alo[NH * NB * ND];
__device__ __nv_bfloat16 g_Bhi[NH * NP * ND];   // [h][n][k] (transposed, padded)
__device__ __nv_bfloat16 g_Blo[NH * NP * ND];
__device__ float g_logits[NH * NB * NC];
__device__ float g_conf[NH * NB];
__device__ float g_logZ[NH * NB];
__device__ int   g_amax[NH * NB];
__device__ float g_loss[NB];
__device__ float g_corr[NB];

// ------------------------- helpers ------------------------------------------
__device__ __forceinline__ uint32_t smem_u32(const void* p) {
    uint32_t a;
    asm("{ .reg .u64 t; cvta.to.shared.u64 t, %1; cvt.u32.u64 %0, t; }" : "=r"(a) : "l"(p));
    return a;
}
__device__ __forceinline__ void cp16(uint32_t dst, const void* src) {
    asm volatile("cp.async.cg.shared.global [%0], [%1], 16;\n" :: "r"(dst), "l"(src) : "memory");
}
__device__ __forceinline__ void cp_commit() {
    asm volatile("cp.async.commit_group;\n" ::: "memory");
}
template<int N> __device__ __forceinline__ void cp_wait() {
    asm volatile("cp.async.wait_group %0;\n" :: "n"(N) : "memory");
}

// SW64-style swizzle for 64B rows: conflict-free ldmatrix + cp.async
__device__ __forceinline__ uint32_t swz_addr(uint32_t base, int row, int colb) {
    return base + (uint32_t)(row * 64 + (colb ^ ((row & 6) << 3)));
}

#define LDSM4(r, a) \
    asm volatile("ldmatrix.sync.aligned.m8n8.x4.shared.b16 {%0,%1,%2,%3}, [%4];" \
        : "=r"((r)[0]), "=r"((r)[1]), "=r"((r)[2]), "=r"((r)[3]) : "r"(a))

#define MMA16816(c, a, b0, b1) \
    asm volatile("mma.sync.aligned.m16n8k16.row.col.f32.bf16.bf16.f32 " \
        "{%0,%1,%2,%3}, {%4,%5,%6,%7}, {%8,%9}, {%0,%1,%2,%3};" \
        : "+f"((c)[0]), "+f"((c)[1]), "+f"((c)[2]), "+f"((c)[3]) \
        : "r"((a)[0]), "r"((a)[1]), "r"((a)[2]), "r"((a)[3]), "r"(b0), "r"(b1))

// ------------------------- conversion kernels -------------------------------
__global__ __launch_bounds__(256) void convA(const float* __restrict__ x) {
    const int i = blockIdx.x * 256 + threadIdx.x;       // over float4, exact grid
    float4 v = ((const float4*)x)[i];
    __nv_bfloat16 h0 = __float2bfloat16(v.x), h1 = __float2bfloat16(v.y);
    __nv_bfloat16 h2 = __float2bfloat16(v.z), h3 = __float2bfloat16(v.w);
    __nv_bfloat16 l0 = __float2bfloat16(v.x - __bfloat162float(h0));
    __nv_bfloat16 l1 = __float2bfloat16(v.y - __bfloat162float(h1));
    __nv_bfloat16 l2 = __float2bfloat16(v.z - __bfloat162float(h2));
    __nv_bfloat16 l3 = __float2bfloat16(v.w - __bfloat162float(h3));
    __nv_bfloat162* ph = (__nv_bfloat162*)g_Ahi;
    __nv_bfloat162* pl = (__nv_bfloat162*)g_Alo;
    ph[2*i]   = __nv_bfloat162(h0, h1);
    ph[2*i+1] = __nv_bfloat162(h2, h3);
    pl[2*i]   = __nv_bfloat162(l0, l1);
    pl[2*i+1] = __nv_bfloat162(l2, l3);
}

// W [h][k][n=1000] fp32 -> Bhi/Blo [h][n=1024][k] bf16 (zero-padded cols)
__global__ __launch_bounds__(256) void convB(const float* __restrict__ W) {
    __shared__ float t[32][33];
    const int h = blockIdx.z;
    const int k0 = blockIdx.y * 32;
    const int n0 = blockIdx.x * 32;
    const int tx = threadIdx.x, ty = threadIdx.y;        // block (32,8)

    #pragma unroll
    for (int i = 0; i < 4; i++) {
        int k = k0 + ty + 8 * i;
        int n = n0 + tx;
        float v = (n < NC) ? W[((size_t)h * ND + k) * NC + n] : 0.f;
        t[ty + 8 * i][tx] = v;
    }
    __syncthreads();
    #pragma unroll
    for (int i = 0; i < 4; i++) {
        int nn = n0 + ty + 8 * i;
        int kk = k0 + tx;
        float v = t[tx][ty + 8 * i];
        __nv_bfloat16 hi = __float2bfloat16(v);
        __nv_bfloat16 lo = __float2bfloat16(v - __bfloat162float(hi));
        size_t idx = ((size_t)h * NP + nn) * ND + kk;
        g_Bhi[idx] = hi;
        g_Blo[idx] = lo;
    }
}

// ------------------------- mma.sync GEMM ------------------------------------
// CTA 128x128, 8 warps (2m x 4n), warp tile 64x32. 3-stage cp.async pipeline.
__global__ void __launch_bounds__(256, 2) gemm_mma(const float* __restrict__ bias) {
    extern __shared__ char sm[];
    const uint32_t sb = smem_u32(sm);
    const int tid = threadIdx.x;
    const int wid = tid >> 5, l = tid & 31;
    const int h  = blockIdx.z;
    const int m0 = blockIdx.y * 128;
    const int n0 = blockIdx.x * 128;

    const __nv_bfloat16* Ah = g_Ahi + ((size_t)h * NB + m0) * ND;
    const __nv_bfloat16* Al = g_Alo + ((size_t)h * NB + m0) * ND;
    const __nv_bfloat16* Bh = g_Bhi + ((size_t)h * NP + n0) * ND;
    const __nv_bfloat16* Bl = g_Blo + ((size_t)h * NP + n0) * ND;

    // stage fill: 2048 x 16B chunks; q8 selects region (compile-time)
    auto load_stage = [&](int s, int kt) {
        const uint32_t base = sb + (uint32_t)s * STG_BYTES;
        #pragma unroll
        for (int q8 = 0; q8 < 8; q8++) {
            const int q = tid + q8 * 256;
            const int r  = q >> 2;          // 0..511
            const int ch = q & 3;
            const __nv_bfloat16* gp;
            uint32_t reg_off;
            int rr;
            if (r < 128)      { gp = Ah + (size_t)r * ND;         reg_off = 0;      rr = r; }
            else if (r < 256) { gp = Al + (size_t)(r - 128) * ND; reg_off = 8192u;  rr = r - 128; }
            else if (r < 384) { gp = Bh + (size_t)(r - 256) * ND; reg_off = 16384u; rr = r - 256; }
            else              { gp = Bl + (size_t)(r - 384) * ND; reg_off = 24576u; rr = r - 384; }
            cp16(swz_addr(base + reg_off, rr, ch * 16), gp + kt + ch * 8);
        }
        cp_commit();
    };

    load_stage(0, 0);
    load_stage(1, BK);

    const int wm = (wid & 1) * 64;
    const int wn = (wid >> 1) * 32;

    float acc[4][4][4];
    #pragma unroll
    for (int a = 0; a < 4; a++)
        #pragma unroll
        for (int b = 0; b < 4; b++)
            #pragma unroll
            for (int c = 0; c < 4; c++) acc[a][b][c] = 0.f;

    const int lrow = l & 15;          // ldmatrix row-in-tile
    const int lcb  = (l >> 4) << 4;   // 0 or 16 bytes (k half)

    for (int it = 0; it < NITER; it++) {
        if (it + 2 < NITER) cp_wait<1>(); else cp_wait<0>();
        __syncthreads();

        if (it + 2 < NITER) load_stage((it + 2) % STAGES, (it + 2) * BK);

        const uint32_t base  = sb + (uint32_t)(it % STAGES) * STG_BYTES;
        const uint32_t abase = base;
        const uint32_t albase = base + 8192u;
        const uint32_t bbase  = base + 16384u;
        const uint32_t blbase = base + 24576u;

        #pragma unroll
        for (int kg = 0; kg < 2; kg++) {
            const int cb = kg * 32 + lcb;
            uint32_t bh_[2][4], bl_[2][4];
            #pragma unroll
            for (int nt = 0; nt < 2; nt++) {
                const int row = wn + nt * 16 + lrow;
                LDSM4(bh_[nt], swz_addr(bbase,  row, cb));
                LDSM4(bl_[nt], swz_addr(blbase, row, cb));
            }
            #pragma unroll
            for (int mt = 0; mt < 4; mt++) {
                uint32_t ah_[4], al_[4];
                const int row = wm + mt * 16 + lrow;
                LDSM4(ah_, swz_addr(abase,  row, cb));
                LDSM4(al_, swz_addr(albase, row, cb));
                #pragma unroll
                for (int nt = 0; nt < 2; nt++) {
                    #pragma unroll
                    for (int hf = 0; hf < 2; hf++) {
                        const int n8 = nt * 2 + hf;
                        MMA16816(acc[mt][n8], ah_, bh_[nt][hf], bh_[nt][hf + 2]);
                        MMA16816(acc[mt][n8], ah_, bl_[nt][hf], bl_[nt][hf + 2]);
                        MMA16816(acc[mt][n8], al_, bh_[nt][hf], bh_[nt][hf + 2]);
                    }
                }
            }
        }
        __syncthreads();
    }

    // epilogue: direct fragment stores (+bias), float2 per (row, n8)
    float bs0[4], bs1[4];
    #pragma unroll
    for (int n8 = 0; n8 < 4; n8++) {
        const int c0 = n0 + wn + n8 * 8 + (l & 3) * 2;
        bs0[n8] = (c0 < NC)     ? bias[h * NC + c0]     : 0.f;
        bs1[n8] = (c0 + 1 < NC) ? bias[h * NC + c0 + 1] : 0.f;
    }
    #pragma unroll
    for (int mt = 0; mt < 4; mt++) {
        const int r0 = m0 + wm + mt * 16 + (l >> 2);
        #pragma unroll
        for (int n8 = 0; n8 < 4; n8++) {
            const int c0 = n0 + wn + n8 * 8 + (l & 3) * 2;
            if (c0 < NC) {
                float2 v0 = make_float2(acc[mt][n8][0] + bs0[n8], acc[mt][n8][1] + bs1[n8]);
                float2 v1 = make_float2(acc[mt][n8][2] + bs0[n8], acc[mt][n8][3] + bs1[n8]);
                *(float2*)&g_logits[((size_t)h * NB + r0) * NC + c0]     = v0;
                *(float2*)&g_logits[((size_t)h * NB + r0 + 8) * NC + c0] = v1;
            }
        }
    }
}

// ------------------------- row stats ----------------------------------------
__global__ __launch_bounds__(128) void rowstats_k() {
    const int row = blockIdx.x;
    const float* lr = g_logits + (size_t)row * NC;
    const int tid = threadIdx.x;

    float vmax = -1e30f; int imax = 0;
    for (int c = tid; c < NC; c += 128) {
        float v = lr[c];
        if (v > vmax) { vmax = v; imax = c; }
    }
    __shared__ float sv[128];
    __shared__ int   si[128];
    sv[tid] = vmax; si[tid] = imax;
    __syncthreads();
    for (int s = 64; s > 0; s >>= 1) {
        if (tid < s) {
            float v2 = sv[tid + s]; int i2 = si[tid + s];
            if (v2 > sv[tid] || (v2 == sv[tid] && i2 < si[tid])) { sv[tid] = v2; si[tid] = i2; }
        }
        __syncthreads();
    }
    const float m = sv[0];
    const int am = si[0];

    float sum = 0.f;
    for (int c = tid; c < NC; c += 128) sum += expf(lr[c] - m);
    __shared__ float ss[128];
    ss[tid] = sum;
    __syncthreads();
    for (int s = 64; s > 0; s >>= 1) {
        if (tid < s) ss[tid] += ss[tid + s];
        __syncthreads();
    }
    if (tid == 0) {
        const float s = ss[0];
        g_conf[row] = 1.f / s;
        g_logZ[row] = m + logf(s);
        g_amax[row] = am;
    }
}

// ------------------------- routing + gather ----------------------------------
__global__ __launch_bounds__(256) void route_k(const int* __restrict__ y_true,
                                               float* __restrict__ out) {
    const int b = blockIdx.x;
    int fh = -1, bh = 0;
    float bc = -1.f;
    #pragma unroll
    for (int hh = 0; hh < NH; hh++) {
        float cv = g_conf[hh * NB + b];
        if (fh < 0 && cv >= TAU) fh = hh;
        if (cv > bc) { bc = cv; bh = hh; }
    }
    const int e = (fh >= 0) ? fh : bh;

    const float* lr = g_logits + ((size_t)e * NB + b) * NC;
    const float4* src = (const float4*)lr;
    float4* dst = (float4*)(out + (size_t)b * NC);
    for (int i = threadIdx.x; i < NC / 4; i += 256) dst[i] = src[i];

    if (threadIdx.x == 0) {
        out[(size_t)NB * NC + b] = (float)e;
        const int y = y_true[b];
        g_loss[b] = -(lr[y] - g_logZ[e * NB + b]);
        g_corr[b] = (g_amax[e * NB + b] == y) ? 1.f : 0.f;
    }
}

__global__ __launch_bounds__(512) void final_k(float* __restrict__ out) {
    __shared__ float sl[512];
    __shared__ float sc[512];
    const int t = threadIdx.x;
    sl[t] = g_loss[t];
    sc[t] = g_corr[t];
    __syncthreads();
    for (int s = 256; s > 0; s >>= 1) {
        if (t < s) { sl[t] += sl[t + s]; sc[t] += sc[t + s]; }
        __syncthreads();
    }
    if (t == 0) {
        out[(size_t)NB * NC + NB + 0] = sl[0] / (float)NB;
        out[(size_t)NB * NC + NB + 1] = sc[0] / (float)NB;
    }
}

// ------------------------- launch --------------------------------------------
extern "C" void kernel_launch(void* const* d_in, const int* in_sizes, int n_in,
                              void* d_out, int out_size) {
    const float* feats = (const float*)d_in[0];   // [6,512,2048]
    const float* Wt    = (const float*)d_in[1];   // [6,2048,1000]
    const float* bias  = (const float*)d_in[2];   // [6,1000]
    const int*   y     = (const int*)d_in[3];     // [512]
    float* out = (float*)d_out;

    cudaFuncSetAttribute(gemm_mma, cudaFuncAttributeMaxDynamicSharedMemorySize, GSMEM);

    convA<<<(NH * NB * ND / 4) / 256, 256>>>(feats);
    convB<<<dim3(32, 64, NH), dim3(32, 8)>>>(Wt);
    gemm_mma<<<dim3(8, 4, NH), 256, GSMEM>>>(bias);
    rowstats_k<<<NH * NB, 128>>>();
    route_k<<<NB, 256>>>(y, out);
    final_k<<<1, 512>>>(out);
}

// round 5
// speedup vs baseline: 2.6445x; 1.2679x over previous
#include <cuda_runtime.h>
#include <cuda_bf16.h>
#include <math.h>
#include <stdint.h>

#define NH 6
#define NB 512
#define ND 2048
#define NC 1000
#define NP 1024
#define TAU 0.5f

#define BK 32
#define NITER (ND / BK)          // 64
#define STAGES 3
#define STG_BYTES (24 * 1024)    // Ahi 4K | Alo 4K | Bhi 8K | Blo 8K
#define GSMEM (STAGES * STG_BYTES)

// ------------------------- scratch ------------------------------------------
__device__ __nv_bfloat16 g_Ahi[NH * NB * ND];
__device__ __nv_bfloat16 g_Alo[NH * NB * ND];
__device__ __nv_bfloat16 g_Bhi[NH * NP * ND];   // [h][n][k]
__device__ __nv_bfloat16 g_Blo[NH * NP * ND];
__device__ float g_logits[NH * NB * NC];
__device__ float g_conf[NH * NB];
__device__ float g_logZ[NH * NB];
__device__ int   g_amax[NH * NB];
__device__ float g_loss[NB];
__device__ float g_corr[NB];

// ------------------------- helpers ------------------------------------------
__device__ __forceinline__ uint32_t smem_u32(const void* p) {
    uint32_t a;
    asm("{ .reg .u64 t; cvta.to.shared.u64 t, %1; cvt.u32.u64 %0, t; }" : "=r"(a) : "l"(p));
    return a;
}
__device__ __forceinline__ void cp16(uint32_t dst, const void* src) {
    asm volatile("cp.async.cg.shared.global [%0], [%1], 16;\n" :: "r"(dst), "l"(src) : "memory");
}
__device__ __forceinline__ void cp_commit() {
    asm volatile("cp.async.commit_group;\n" ::: "memory");
}
template<int N> __device__ __forceinline__ void cp_wait() {
    asm volatile("cp.async.wait_group %0;\n" :: "n"(N) : "memory");
}
__device__ __forceinline__ uint32_t swz_addr(uint32_t base, int row, int colb) {
    return base + (uint32_t)(row * 64 + (colb ^ ((row & 6) << 3)));
}
#define LDSM4(r, a) \
    asm volatile("ldmatrix.sync.aligned.m8n8.x4.shared.b16 {%0,%1,%2,%3}, [%4];" \
        : "=r"((r)[0]), "=r"((r)[1]), "=r"((r)[2]), "=r"((r)[3]) : "r"(a))
#define MMA16816(c, a, b0, b1) \
    asm volatile("mma.sync.aligned.m16n8k16.row.col.f32.bf16.bf16.f32 " \
        "{%0,%1,%2,%3}, {%4,%5,%6,%7}, {%8,%9}, {%0,%1,%2,%3};" \
        : "+f"((c)[0]), "+f"((c)[1]), "+f"((c)[2]), "+f"((c)[3]) \
        : "r"((a)[0]), "r"((a)[1]), "r"((a)[2]), "r"((a)[3]), "r"(b0), "r"(b1))

// ------------------------- merged conversion kernel --------------------------
// blocks [0, NA_BLK): A split (elementwise).  blocks [NA_BLK, ...): B transpose+split.
#define NA_BLK (NH * NB * ND / 4 / 256)      // 6144

__global__ __launch_bounds__(256) void conv_all(const float* __restrict__ x,
                                                const float* __restrict__ W) {
    const int tid = threadIdx.x;
    if (blockIdx.x < NA_BLK) {
        const int i = blockIdx.x * 256 + tid;
        float4 v = ((const float4*)x)[i];
        __nv_bfloat16 h0 = __float2bfloat16(v.x), h1 = __float2bfloat16(v.y);
        __nv_bfloat16 h2 = __float2bfloat16(v.z), h3 = __float2bfloat16(v.w);
        __nv_bfloat16 l0 = __float2bfloat16(v.x - __bfloat162float(h0));
        __nv_bfloat16 l1 = __float2bfloat16(v.y - __bfloat162float(h1));
        __nv_bfloat16 l2 = __float2bfloat16(v.z - __bfloat162float(h2));
        __nv_bfloat16 l3 = __float2bfloat16(v.w - __bfloat162float(h3));
        __nv_bfloat162* ph = (__nv_bfloat162*)g_Ahi;
        __nv_bfloat162* pl = (__nv_bfloat162*)g_Alo;
        ph[2*i]   = __nv_bfloat162(h0, h1);
        ph[2*i+1] = __nv_bfloat162(h2, h3);
        pl[2*i]   = __nv_bfloat162(l0, l1);
        pl[2*i+1] = __nv_bfloat162(l2, l3);
        return;
    }
    // ---- B role: W [h][k][n] fp32 -> g_B{hi,lo} [h][n(1024)][k] bf16
    __shared__ float t[32][33];
    const int bi = blockIdx.x - NA_BLK;
    const int n0 = (bi & 31) * 32;
    const int k0 = ((bi >> 5) & 63) * 32;
    const int h  = bi >> 11;

    const int tx = tid & 31, ty = tid >> 5;      // (32, 8)
    #pragma unroll
    for (int i = 0; i < 4; i++) {
        int k = k0 + ty + 8 * i;
        int n = n0 + tx;
        t[ty + 8 * i][tx] = (n < NC) ? W[((size_t)h * ND + k) * NC + n] : 0.f;
    }
    __syncthreads();

    // 256 threads: arr(hi/lo) x 32 n-rows x 4 k-groups; one 16B store each
    const int u  = tid & 127;
    const int nn = u >> 2;
    const int kg = u & 3;
    const int isLo = tid >> 7;
    __nv_bfloat16 vals[8];
    #pragma unroll
    for (int j = 0; j < 8; j++) {
        float v = t[kg * 8 + j][nn];
        __nv_bfloat16 hi = __float2bfloat16(v);
        vals[j] = isLo ? __float2bfloat16(v - __bfloat162float(hi)) : hi;
    }
    __nv_bfloat16* dst = (isLo ? g_Blo : g_Bhi)
                       + ((size_t)h * NP + n0 + nn) * ND + k0 + kg * 8;
    *(uint4*)dst = *(uint4*)vals;
}

// ------------------------- mma.sync GEMM ------------------------------------
// CTA 64(M)x128(N), 4 warps (warp tile 64x32), BK=32, 3-stage cp.async.
__global__ void __launch_bounds__(128, 3) gemm_mma(const float* __restrict__ bias) {
    extern __shared__ char sm[];
    const uint32_t sb = smem_u32(sm);
    const int tid = threadIdx.x;
    const int wid = tid >> 5, l = tid & 31;
    const int h  = blockIdx.z;
    const int m0 = blockIdx.y * 64;
    const int n0 = blockIdx.x * 128;

    const __nv_bfloat16* Ah = g_Ahi + ((size_t)h * NB + m0) * ND;
    const __nv_bfloat16* Al = g_Alo + ((size_t)h * NB + m0) * ND;
    const __nv_bfloat16* Bh = g_Bhi + ((size_t)h * NP + n0) * ND;
    const __nv_bfloat16* Bl = g_Blo + ((size_t)h * NP + n0) * ND;

    // stage: 1536 x 16B chunks (Ahi 64r | Alo 64r | Bhi 128r | Blo 128r), 64B rows
    auto load_stage = [&](int s, int kt) {
        const uint32_t base = sb + (uint32_t)s * STG_BYTES;
        #pragma unroll
        for (int q12 = 0; q12 < 12; q12++) {
            const int q = tid + q12 * 128;
            const int r  = q >> 2;          // 0..383
            const int ch = q & 3;
            const __nv_bfloat16* gp;
            uint32_t reg_off;
            int rr;
            if (r < 64)       { gp = Ah + (size_t)r * ND;         reg_off = 0;      rr = r; }
            else if (r < 128) { gp = Al + (size_t)(r - 64) * ND;  reg_off = 4096u;  rr = r - 64; }
            else if (r < 256) { gp = Bh + (size_t)(r - 128) * ND; reg_off = 8192u;  rr = r - 128; }
            else              { gp = Bl + (size_t)(r - 256) * ND; reg_off = 16384u; rr = r - 256; }
            cp16(swz_addr(base + reg_off, rr, ch * 16), gp + kt + ch * 8);
        }
        cp_commit();
    };

    load_stage(0, 0);
    load_stage(1, BK);

    const int wn = wid * 32;

    float acc[4][4][4];
    #pragma unroll
    for (int a = 0; a < 4; a++)
        #pragma unroll
        for (int b = 0; b < 4; b++)
            #pragma unroll
            for (int c = 0; c < 4; c++) acc[a][b][c] = 0.f;

    const int lrow = l & 15;
    const int lcb  = (l >> 4) << 4;

    for (int it = 0; it < NITER; it++) {
        if (it + 2 < NITER) cp_wait<1>(); else cp_wait<0>();
        __syncthreads();

        if (it + 2 < NITER) load_stage((it + 2) % STAGES, (it + 2) * BK);

        const uint32_t base   = sb + (uint32_t)(it % STAGES) * STG_BYTES;
        const uint32_t abase  = base;
        const uint32_t albase = base + 4096u;
        const uint32_t bbase  = base + 8192u;
        const uint32_t blbase = base + 16384u;

        #pragma unroll
        for (int kg = 0; kg < 2; kg++) {
            const int cb = kg * 32 + lcb;
            uint32_t bh_[2][4], bl_[2][4];
            #pragma unroll
            for (int nt = 0; nt < 2; nt++) {
                const int row = wn + nt * 16 + lrow;
                LDSM4(bh_[nt], swz_addr(bbase,  row, cb));
                LDSM4(bl_[nt], swz_addr(blbase, row, cb));
            }
            #pragma unroll
            for (int mt = 0; mt < 4; mt++) {
                uint32_t ah_[4], al_[4];
                const int row = mt * 16 + lrow;
                LDSM4(ah_, swz_addr(abase,  row, cb));
                LDSM4(al_, swz_addr(albase, row, cb));
                #pragma unroll
                for (int nt = 0; nt < 2; nt++) {
                    #pragma unroll
                    for (int hf = 0; hf < 2; hf++) {
                        const int n8 = nt * 2 + hf;
                        MMA16816(acc[mt][n8], ah_, bh_[nt][hf], bh_[nt][hf + 2]);
                        MMA16816(acc[mt][n8], ah_, bl_[nt][hf], bl_[nt][hf + 2]);
                        MMA16816(acc[mt][n8], al_, bh_[nt][hf], bh_[nt][hf + 2]);
                    }
                }
            }
        }
        __syncthreads();
    }

    // epilogue
    float bs0[4], bs1[4];
    #pragma unroll
    for (int n8 = 0; n8 < 4; n8++) {
        const int c0 = n0 + wn + n8 * 8 + (l & 3) * 2;
        bs0[n8] = (c0 < NC)     ? bias[h * NC + c0]     : 0.f;
        bs1[n8] = (c0 + 1 < NC) ? bias[h * NC + c0 + 1] : 0.f;
    }
    #pragma unroll
    for (int mt = 0; mt < 4; mt++) {
        const int r0 = m0 + mt * 16 + (l >> 2);
        #pragma unroll
        for (int n8 = 0; n8 < 4; n8++) {
            const int c0 = n0 + wn + n8 * 8 + (l & 3) * 2;
            if (c0 < NC) {
                float2 v0 = make_float2(acc[mt][n8][0] + bs0[n8], acc[mt][n8][1] + bs1[n8]);
                float2 v1 = make_float2(acc[mt][n8][2] + bs0[n8], acc[mt][n8][3] + bs1[n8]);
                *(float2*)&g_logits[((size_t)h * NB + r0) * NC + c0]     = v0;
                *(float2*)&g_logits[((size_t)h * NB + r0 + 8) * NC + c0] = v1;
            }
        }
    }
}

// ------------------------- row stats: single pass, float4 --------------------
__global__ __launch_bounds__(256) void rowstats_k() {
    const int row = blockIdx.x;
    const float4* lr = (const float4*)(g_logits + (size_t)row * NC);
    const int tid = threadIdx.x;

    float4 v = make_float4(-1e30f, -1e30f, -1e30f, -1e30f);
    if (tid < NC / 4) v = lr[tid];

    // local (max, argmax) — first occurrence wins
    float vmax = v.x; int imax = tid * 4;
    if (v.y > vmax) { vmax = v.y; imax = tid * 4 + 1; }
    if (v.z > vmax) { vmax = v.z; imax = tid * 4 + 2; }
    if (v.w > vmax) { vmax = v.w; imax = tid * 4 + 3; }

    #pragma unroll
    for (int off = 16; off > 0; off >>= 1) {
        float ov = __shfl_down_sync(0xffffffffu, vmax, off);
        int   oi = __shfl_down_sync(0xffffffffu, imax, off);
        if (ov > vmax || (ov == vmax && oi < imax)) { vmax = ov; imax = oi; }
    }
    __shared__ float swv[8];
    __shared__ int   swi[8];
    const int w = tid >> 5;
    if ((tid & 31) == 0) { swv[w] = vmax; swi[w] = imax; }
    __syncthreads();
    if (tid < 8) {
        vmax = swv[tid]; imax = swi[tid];
        #pragma unroll
        for (int off = 4; off > 0; off >>= 1) {
            float ov = __shfl_down_sync(0xffu, vmax, off);
            int   oi = __shfl_down_sync(0xffu, imax, off);
            if (ov > vmax || (ov == vmax && oi < imax)) { vmax = ov; imax = oi; }
        }
        if (tid == 0) { swv[0] = vmax; swi[0] = imax; }
    }
    __syncthreads();
    const float m = swv[0];

    float sum = __expf(v.x - m) + __expf(v.y - m) + __expf(v.z - m) + __expf(v.w - m);
    #pragma unroll
    for (int off = 16; off > 0; off >>= 1)
        sum += __shfl_down_sync(0xffffffffu, sum, off);
    __shared__ float sws[8];
    if ((tid & 31) == 0) sws[w] = sum;
    __syncthreads();
    if (tid == 0) {
        float s = 0.f;
        #pragma unroll
        for (int i = 0; i < 8; i++) s += sws[i];
        g_conf[row] = 1.f / s;
        g_logZ[row] = m + logf(s);
        g_amax[row] = swi[0];
    }
}

// ------------------------- routing + gather ----------------------------------
__global__ __launch_bounds__(256) void route_k(const int* __restrict__ y_true,
                                               float* __restrict__ out) {
    const int b = blockIdx.x;
    int fh = -1, bh = 0;
    float bc = -1.f;
    #pragma unroll
    for (int hh = 0; hh < NH; hh++) {
        float cv = g_conf[hh * NB + b];
        if (fh < 0 && cv >= TAU) fh = hh;
        if (cv > bc) { bc = cv; bh = hh; }
    }
    const int e = (fh >= 0) ? fh : bh;

    const float* lr = g_logits + ((size_t)e * NB + b) * NC;
    const float4* src = (const float4*)lr;
    float4* dst = (float4*)(out + (size_t)b * NC);
    if (threadIdx.x < NC / 4) dst[threadIdx.x] = src[threadIdx.x];

    if (threadIdx.x == 0) {
        out[(size_t)NB * NC + b] = (float)e;
        const int y = y_true[b];
        g_loss[b] = -(lr[y] - g_logZ[e * NB + b]);
        g_corr[b] = (g_amax[e * NB + b] == y) ? 1.f : 0.f;
    }
}

__global__ __launch_bounds__(512) void final_k(float* __restrict__ out) {
    __shared__ float sl[512];
    __shared__ float sc[512];
    const int t = threadIdx.x;
    sl[t] = g_loss[t];
    sc[t] = g_corr[t];
    __syncthreads();
    for (int s = 256; s > 0; s >>= 1) {
        if (t < s) { sl[t] += sl[t + s]; sc[t] += sc[t + s]; }
        __syncthreads();
    }
    if (t == 0) {
        out[(size_t)NB * NC + NB + 0] = sl[0] / (float)NB;
        out[(size_t)NB * NC + NB + 1] = sc[0] / (float)NB;
    }
}

// ------------------------- launch --------------------------------------------
extern "C" void kernel_launch(void* const* d_in, const int* in_sizes, int n_in,
                              void* d_out, int out_size) {
    const float* feats = (const float*)d_in[0];
    const float* Wt    = (const float*)d_in[1];
    const float* bias  = (const float*)d_in[2];
    const int*   y     = (const int*)d_in[3];
    float* out = (float*)d_out;

    cudaFuncSetAttribute(gemm_mma, cudaFuncAttributeMaxDynamicSharedMemorySize, GSMEM);

    conv_all<<<NA_BLK + 32 * 64 * NH, 256>>>(feats, Wt);
    gemm_mma<<<dim3(8, 8, NH), 128, GSMEM>>>(bias);
    rowstats_k<<<NH * NB, 256>>>();
    route_k<<<NB, 256>>>(y, out);
    final_k<<<1, 512>>>(out);
}